// round 1
// baseline (speedup 1.0000x reference)
#include <cuda_runtime.h>

// ARModel: self-feeding AR(P) recurrence.
//   h0[b,n,:] = x[b, T-P : T, n, 0]
//   for t in 0..T-1: pred = dot(ar[n,:], h) + bias[n]; h = shift(h, pred); out[b,t,n] = pred
//
// One thread per (b, n) sequence. History kept in a P-register rotating window;
// T loop unrolled by P so rotation is static register renaming (no shift MOVs).

constexpr int Bd = 64;
constexpr int Td = 288;
constexpr int Nd = 1024;
constexpr int Pd = 12;

static_assert(Td % Pd == 0, "T must be a multiple of P for the rotation unroll");

__global__ void __launch_bounds__(256, 8)
ar_model_kernel(const float* __restrict__ x,
                const float* __restrict__ ar,
                const float* __restrict__ bias,
                float* __restrict__ out)
{
    const int n = blockIdx.x * blockDim.x + threadIdx.x;  // node index, coalesced
    const int b = blockIdx.y;                             // batch index
    if (n >= Nd) return;

    // Per-node AR coefficients + bias (48 B/thread, L2-resident after first touch)
    float a[Pd];
#pragma unroll
    for (int j = 0; j < Pd; ++j) a[j] = ar[n * Pd + j];
    const float bi = bias[n];

    // Initial history: last P input timesteps. buf[j] = x[b, T-P+j, n]; oldest at index 0.
    float buf[Pd];
#pragma unroll
    for (int j = 0; j < Pd; ++j)
        buf[j] = x[((size_t)b * Td + (Td - Pd + j)) * Nd + n];

    float* o = out + (size_t)b * Td * Nd + n;

    for (int tb = 0; tb < Td; tb += Pd) {
#pragma unroll
        for (int s = 0; s < Pd; ++s) {
            // At sub-step s the oldest history element sits at buf[s % P];
            // logical h[j] = buf[(s + j) % P]. All indices constant after unroll.
            float pred = bi;
#pragma unroll
            for (int j = 0; j < Pd; ++j)
                pred = fmaf(a[j], buf[(s + j) % Pd], pred);
            buf[s] = pred;                    // new value replaces oldest slot
            o[(size_t)(tb + s) * Nd] = pred;  // coalesced across the warp
        }
    }
}

extern "C" void kernel_launch(void* const* d_in, const int* in_sizes, int n_in,
                              void* d_out, int out_size)
{
    const float* x    = (const float*)d_in[0];  // (B, T, N, 1) fp32
    const float* ar   = (const float*)d_in[1];  // (N, P) fp32
    const float* bias = (const float*)d_in[2];  // (N,) fp32
    float* out = (float*)d_out;                 // (B, T, N, 1) fp32

    dim3 block(256);
    dim3 grid(Nd / 256, Bd);
    ar_model_kernel<<<grid, block>>>(x, ar, bias, out);
}

// round 2
// speedup vs baseline: 1.6122x; 1.6122x over previous
#include <cuda_runtime.h>

// ARModel: self-feeding AR(P), linearized k-step-ahead expansion + f32x2 packing.
//
// pred_{t+m} = beta_m * bias + c^m . h_t   (h_t = 12-entry window, oldest first)
//   c^0 = a;  c^{m+1}_j = c^m_{j-1} (0 if j==0) + c^m_{P-1} * a_j
//   beta_0 = 1; beta_1 = 1 + a11; beta_2 = 1 + a10 + a11*beta_1
// Each round emits k=3 independent predictions from one window -> FMA chain
// no longer serializes consecutive timesteps.
//
// Each thread handles TWO adjacent nodes (n0, n0+1) packed into f32x2 lanes:
// all math via fma.rn.f32x2 (SASS FFMA2), all global traffic 8-byte and
// coalesced across the warp.

constexpr int Bd = 64;
constexpr int Td = 288;
constexpr int Nd = 1024;
constexpr int Pd = 12;
constexpr int K  = 3;              // steps per round
static_assert(Td % Pd == 0 && Pd % K == 0, "unroll structure");

typedef unsigned long long u64;

__device__ __forceinline__ u64 pack2(float lo, float hi) {
    u64 r; asm("mov.b64 %0, {%1, %2};" : "=l"(r) : "f"(lo), "f"(hi)); return r;
}
__device__ __forceinline__ u64 fma2(u64 a, u64 b, u64 c) {
    u64 d; asm("fma.rn.f32x2 %0, %1, %2, %3;" : "=l"(d) : "l"(a), "l"(b), "l"(c)); return d;
}
__device__ __forceinline__ u64 mul2(u64 a, u64 b) {
    u64 d; asm("mul.rn.f32x2 %0, %1, %2;" : "=l"(d) : "l"(a), "l"(b)); return d;
}

__global__ void __launch_bounds__(32)
ar_model_f32x2_kernel(const float* __restrict__ x,
                      const float* __restrict__ ar,
                      const float* __restrict__ bias,
                      float* __restrict__ out)
{
    const int tid = blockIdx.x * 32 + threadIdx.x;   // 0 .. 32767
    const int b   = tid >> 9;                        // batch  (tid / 512)
    const int pr  = tid & 511;                       // node pair
    const int n0  = pr * 2;

    // ---- pack per-node AR coefficients: a[j] = (ar[n0][j], ar[n0+1][j]) ----
    float alo[Pd], ahi[Pd];
#pragma unroll
    for (int j = 0; j < Pd; ++j) {
        alo[j] = ar[n0 * Pd + j];
        ahi[j] = ar[(n0 + 1) * Pd + j];
    }
    u64 a[Pd];
#pragma unroll
    for (int j = 0; j < Pd; ++j) a[j] = pack2(alo[j], ahi[j]);

    // ---- expanded coefficients c1 = aM, c2 = aM^2 (companion matrix M) ----
    u64 c1[Pd], c2[Pd];
    c1[0] = mul2(a[Pd - 1], a[0]);
#pragma unroll
    for (int j = 1; j < Pd; ++j) c1[j] = fma2(a[Pd - 1], a[j], a[j - 1]);
    c2[0] = mul2(c1[Pd - 1], a[0]);
#pragma unroll
    for (int j = 1; j < Pd; ++j) c2[j] = fma2(c1[Pd - 1], a[j], c1[j - 1]);

    // ---- bias premultipliers: bb_m = beta_m * bias (per lane) ----
    const float blo = bias[n0], bhi = bias[n0 + 1];
    const float b1lo = 1.0f + alo[11],                 b1hi = 1.0f + ahi[11];
    const float b2lo = 1.0f + alo[10] + alo[11] * b1lo,
                b2hi = 1.0f + ahi[10] + ahi[11] * b1hi;
    const u64 bb0 = pack2(blo, bhi);
    const u64 bb1 = pack2(b1lo * blo, b1hi * bhi);
    const u64 bb2 = pack2(b2lo * blo, b2hi * bhi);

    // ---- initial history window: last P input timesteps (oldest first) ----
    u64 buf[Pd];
    const u64* xr = reinterpret_cast<const u64*>(
        x + ((size_t)b * Td + (Td - Pd)) * Nd + n0);
#pragma unroll
    for (int j = 0; j < Pd; ++j) buf[j] = xr[(size_t)j * (Nd / 2)];

    u64* o = reinterpret_cast<u64*>(out + (size_t)b * Td * Nd + n0);
    constexpr int ST = Nd / 2;                       // timestep stride in u64

    for (int r = 0; r < Td / Pd; ++r) {              // 24 iterations x 12 steps
#pragma unroll
        for (int ph = 0; ph < Pd / K; ++ph) {        // 4 phases, off = 0,3,6,9
            const int off = ph * K;
            u64 p0 = bb0, p1 = bb1, p2 = bb2;        // 3 independent dot products
#pragma unroll
            for (int j = 0; j < Pd; ++j) {
                const u64 h = buf[(off + j) % Pd];   // constant index post-unroll
                p0 = fma2(a[j],  h, p0);
                p1 = fma2(c1[j], h, p1);
                p2 = fma2(c2[j], h, p2);
            }
            // rotate: the 3 oldest slots are replaced by the 3 new predictions
            buf[off]     = p0;
            buf[off + 1] = p1;
            buf[off + 2] = p2;
            o[0]      = p0;                           // t   = (r*4+ph)*3
            o[ST]     = p1;                           // t+1
            o[2 * ST] = p2;                           // t+2
            o += 3 * ST;
        }
    }
}

extern "C" void kernel_launch(void* const* d_in, const int* in_sizes, int n_in,
                              void* d_out, int out_size)
{
    const float* x    = (const float*)d_in[0];  // (B, T, N, 1) fp32
    const float* ar   = (const float*)d_in[1];  // (N, P) fp32
    const float* bias = (const float*)d_in[2];  // (N,) fp32
    float* out = (float*)d_out;

    // 64 * 512 node-pairs = 32768 threads; 32-thread blocks -> 1024 blocks
    // spread ~6.9 warps/SM with near-perfect wave balance.
    ar_model_f32x2_kernel<<<(Bd * (Nd / 2)) / 32, 32>>>(x, ar, bias, out);
}